// round 1
// baseline (speedup 1.0000x reference)
#include <cuda_runtime.h>
#include <math.h>

#define NATOMS 65536
#define NBLK   256
#define TPB    256
#define NM     6
#define LMAX   6
#define LL     7
#define NC     (NM*LL*LL)   // 294
#define RCF    6.0f
#define RCINV  (1.0f/6.0f)

__device__ float g_part[NBLK * NC];
__device__ float g_c[NC];

struct D4 { float v, gx, gy, gz; };

__device__ __forceinline__ float warp_sum(float v){
    v += __shfl_xor_sync(0xffffffffu, v, 16);
    v += __shfl_xor_sync(0xffffffffu, v, 8);
    v += __shfl_xor_sync(0xffffffffu, v, 4);
    v += __shfl_xor_sync(0xffffffffu, v, 2);
    v += __shfl_xor_sync(0xffffffffu, v, 1);
    return v;
}

// ---------------------------------------------------------------------------
// Pass 1: per-atom Y values + radial f, deterministic block-partial c.
// ---------------------------------------------------------------------------
__global__ void __launch_bounds__(TPB) pass1(const float* __restrict__ xyz){
    __shared__ float wsh[TPB/32][NC];   // per-warp partials (deterministic)
    const int t = threadIdx.x;
    const int warp = t >> 5, lane = t & 31;
    const int j = blockIdx.x * TPB + t;

    const float x = xyz[3*j+0], y = xyz[3*j+1], z = xyz[3*j+2];
    const float r2 = x*x + y*y + z*z;
    const float d  = sqrtf(r2);
    const float tc = 1.0f - d*RCINV;
    const float rcut = (d < RCF) ? tc*tc : 0.0f;

    float f[NM];
    f[0] = rcut;
    #pragma unroll
    for (int n = 1; n < NM; n++) f[n] = f[n-1]*r2;

    float re[LL][LL], im[LL][LL];
    re[0][0] = 0.28209479177387814f; im[0][0] = 0.0f;
    #pragma unroll
    for (int l = 1; l < LL; l++){
        const float al = -sqrtf((2.0f*l + 1.0f)/(2.0f*l));
        re[l][l] = al*(x*re[l-1][l-1] - y*im[l-1][l-1]);
        im[l][l] = al*(x*im[l-1][l-1] + y*re[l-1][l-1]);
        #pragma unroll
        for (int m = 0; m < l; m++){
            const float invA = rsqrtf((float)(l*l - m*m)/((2.0f*l-1.0f)*(2.0f*l+1.0f)));
            if (l - 2 >= m){
                const float Ap = sqrtf((float)((l-1)*(l-1) - m*m)/((2.0f*l-3.0f)*(2.0f*l-1.0f)));
                re[l][m] = (z*re[l-1][m] - Ap*r2*re[l-2][m])*invA;
                im[l][m] = (z*im[l-1][m] - Ap*r2*im[l-2][m])*invA;
            } else {
                re[l][m] = z*re[l-1][m]*invA;
                im[l][m] = z*im[l-1][m]*invA;
            }
        }
    }

    // Packed matrix: Yp[i][jj] = (jj<=i) ? re(i, i-jj) : im(jj, i+1)
    #pragma unroll
    for (int i = 0; i < LL; i++){
        #pragma unroll
        for (int jj = 0; jj < LL; jj++){
            const float yv = (jj <= i) ? re[i][i-jj] : im[jj][i+1];
            #pragma unroll
            for (int b = 0; b < NM; b++){
                const float v = warp_sum(f[b]*yv);
                if (lane == 0) wsh[warp][(b*LL + i)*LL + jj] = v;
            }
        }
    }
    __syncthreads();
    for (int i = t; i < NC; i += TPB){
        float s = 0.0f;
        #pragma unroll
        for (int w = 0; w < TPB/32; w++) s += wsh[w][i];
        g_part[blockIdx.x*NC + i] = s;
    }
}

// ---------------------------------------------------------------------------
// Reduce partials -> c, compute p (first 252 outputs). One block.
// ---------------------------------------------------------------------------
__global__ void __launch_bounds__(320) reduce_c(float* __restrict__ out){
    __shared__ float csh[NC];
    const int t = threadIdx.x;
    if (t < NC){
        float s = 0.0f;
        for (int bk = 0; bk < NBLK; bk++) s += g_part[bk*NC + t];
        g_c[t] = s;
        csh[t] = s;
    }
    __syncthreads();
    if (t < LL*NM*NM){   // 252
        const int l = t / 36;
        const int a = (t / 6) % 6;
        const int b = t % 6;
        const float* ca = &csh[a*49];
        const float* cb = &csh[b*49];
        float s = 0.0f;
        for (int m = 0; m <= l; m++){
            const float w = (m == l) ? 1.0f : 2.0f;
            s += w * ca[l*7 + m] * cb[l*7 + m];
        }
        for (int lp = 0; lp < l; lp++){
            s += 2.0f * ca[lp*7 + l] * cb[lp*7 + l];
        }
        out[t] = s;
    }
}

// ---------------------------------------------------------------------------
// Pass 2: per-atom dual recursion (value + analytic gradient), streamed per l;
// emit dp[l,a,b,j,0..2] with coalesced stores.
// ---------------------------------------------------------------------------
__global__ void __launch_bounds__(TPB,1) pass2(const float* __restrict__ xyz,
                                               float* __restrict__ out){
    __shared__ float csh[NC];
    const int t = threadIdx.x;
    for (int i = t; i < NC; i += TPB) csh[i] = g_c[i];
    __syncthreads();

    const int j = blockIdx.x * TPB + t;
    const float x = xyz[3*j+0], y = xyz[3*j+1], z = xyz[3*j+2];
    const float r2 = x*x + y*y + z*z;
    const float invd = rsqrtf(r2);
    const float d = r2 * invd;
    const float ux = x*invd, uy = y*invd, uz = z*invd;

    const float tc = 1.0f - d*RCINV;
    const bool  in = (d < RCF);
    const float rcut = in ? tc*tc : 0.0f;
    const float drc  = in ? (-2.0f*RCINV)*tc : 0.0f;

    float f[NM], dfx[NM], dfy[NM], dfz[NM];
    {
        float p2 = 1.0f;
        #pragma unroll
        for (int n = 0; n < NM; n++){
            f[n] = rcut * p2;
            const float dfn = drc*p2 + rcut * (2.0f*n) * p2 * invd;
            dfx[n] = dfn*ux; dfy[n] = dfn*uy; dfz[n] = dfn*uz;
            p2 *= r2;
        }
    }

    float* po = out + 252 + 3*(size_t)j;
    const size_t stride = (size_t)3 * NATOMS;

    D4 Re[LL][LL], Im[LL][LL];
    Re[0][0].v = 0.28209479177387814f; Re[0][0].gx = 0.f; Re[0][0].gy = 0.f; Re[0][0].gz = 0.f;
    Im[0][0].v = 0.f; Im[0][0].gx = 0.f; Im[0][0].gy = 0.f; Im[0][0].gz = 0.f;

    #pragma unroll
    for (int l = 0; l < LL; l++){
        if (l > 0){
            const float al = -sqrtf((2.0f*l + 1.0f)/(2.0f*l));
            {
                const D4 rp = Re[l-1][l-1], ip = Im[l-1][l-1];
                Re[l][l].v  = al*(x*rp.v - y*ip.v);
                Re[l][l].gx = al*(rp.v + x*rp.gx - y*ip.gx);
                Re[l][l].gy = al*(x*rp.gy - ip.v - y*ip.gy);
                Re[l][l].gz = al*(x*rp.gz - y*ip.gz);
                Im[l][l].v  = al*(x*ip.v + y*rp.v);
                Im[l][l].gx = al*(ip.v + x*ip.gx + y*rp.gx);
                Im[l][l].gy = al*(x*ip.gy + rp.v + y*rp.gy);
                Im[l][l].gz = al*(x*ip.gz + y*rp.gz);
            }
            #pragma unroll
            for (int m = 0; m < l; m++){
                const float invA = rsqrtf((float)(l*l - m*m)/((2.0f*l-1.0f)*(2.0f*l+1.0f)));
                const D4 a1r = Re[l-1][m], a1i = Im[l-1][m];
                if (l - 2 >= m){
                    const float Ap = sqrtf((float)((l-1)*(l-1) - m*m)/((2.0f*l-3.0f)*(2.0f*l-1.0f)));
                    const D4 a2r = Re[l-2][m], a2i = Im[l-2][m];
                    Re[l][m].v  = (z*a1r.v  - Ap*r2*a2r.v)*invA;
                    Re[l][m].gx = (z*a1r.gx - Ap*(r2*a2r.gx + 2.0f*x*a2r.v))*invA;
                    Re[l][m].gy = (z*a1r.gy - Ap*(r2*a2r.gy + 2.0f*y*a2r.v))*invA;
                    Re[l][m].gz = (a1r.v + z*a1r.gz - Ap*(r2*a2r.gz + 2.0f*z*a2r.v))*invA;
                    Im[l][m].v  = (z*a1i.v  - Ap*r2*a2i.v)*invA;
                    Im[l][m].gx = (z*a1i.gx - Ap*(r2*a2i.gx + 2.0f*x*a2i.v))*invA;
                    Im[l][m].gy = (z*a1i.gy - Ap*(r2*a2i.gy + 2.0f*y*a2i.v))*invA;
                    Im[l][m].gz = (a1i.v + z*a1i.gz - Ap*(r2*a2i.gz + 2.0f*z*a2i.v))*invA;
                } else {
                    Re[l][m].v  = z*a1r.v*invA;
                    Re[l][m].gx = z*a1r.gx*invA;
                    Re[l][m].gy = z*a1r.gy*invA;
                    Re[l][m].gz = (a1r.v + z*a1r.gz)*invA;
                    Im[l][m].v  = z*a1i.v*invA;
                    Im[l][m].gx = z*a1i.gx*invA;
                    Im[l][m].gy = z*a1i.gy*invA;
                    Im[l][m].gz = (a1i.v + z*a1i.gz)*invA;
                }
            }
        }

        // G[b] and H[b][.] for this l
        float G[NM]  = {0,0,0,0,0,0};
        float Hx[NM] = {0,0,0,0,0,0};
        float Hy[NM] = {0,0,0,0,0,0};
        float Hz[NM] = {0,0,0,0,0,0};
        #pragma unroll
        for (int m = 0; m <= l; m++){
            const float w = (m == 0) ? 1.0f : 2.0f;
            const D4 rr = Re[l][m];
            #pragma unroll
            for (int b = 0; b < NM; b++){
                const float wc = w * csh[b*49 + l*7 + (l - m)];
                G[b]  += wc*rr.v;
                Hx[b] += wc*rr.gx;
                Hy[b] += wc*rr.gy;
                Hz[b] += wc*rr.gz;
            }
        }
        #pragma unroll
        for (int m = 1; m <= l; m++){
            const D4 ii = Im[l][m];
            #pragma unroll
            for (int b = 0; b < NM; b++){
                const float wc = 2.0f * csh[b*49 + (m-1)*7 + l];
                G[b]  += wc*ii.v;
                Hx[b] += wc*ii.gx;
                Hy[b] += wc*ii.gy;
                Hz[b] += wc*ii.gz;
            }
        }

        // Emit dp[l,a,b,j,k] = dfv[a,k]G[b] + f[a]H[b,k] + dfv[b,k]G[a] + f[b]H[a,k]
        #pragma unroll
        for (int a = 0; a < NM; a++){
            #pragma unroll
            for (int b = 0; b < NM; b++){
                po[0] = dfx[a]*G[b] + f[a]*Hx[b] + dfx[b]*G[a] + f[b]*Hx[a];
                po[1] = dfy[a]*G[b] + f[a]*Hy[b] + dfy[b]*G[a] + f[b]*Hy[a];
                po[2] = dfz[a]*G[b] + f[a]*Hz[b] + dfz[b]*G[a] + f[b]*Hz[a];
                po += stride;
            }
        }
    }
}

// ---------------------------------------------------------------------------
extern "C" void kernel_launch(void* const* d_in, const int* in_sizes, int n_in,
                              void* d_out, int out_size){
    const float* xyz = (const float*)d_in[0];
    float* out = (float*)d_out;
    pass1<<<NBLK, TPB>>>(xyz);
    reduce_c<<<1, 320>>>(out);
    pass2<<<NBLK, TPB>>>(xyz, out);
}

// round 2
// speedup vs baseline: 1.0257x; 1.0257x over previous
#include <cuda_runtime.h>
#include <math.h>

#define NATOMS 65536
#define NM     6
#define LL     7
#define NC     (NM*LL*LL)   // 294
#define RCF    6.0f
#define RCINV  (1.0f/6.0f)

// pass1: 2 threads per atom, 128 atoms per 256-thread block
#define TPB1   256
#define APB    128
#define NBLK1  (NATOMS/APB)  // 512

// pass2: 1 atom per thread
#define TPB2   256
#define NBLK2  (NATOMS/TPB2) // 256

__device__ float g_part[NBLK1 * NC];
__device__ float g_c[NC];

struct D4 { float v, gx, gy, gz; };

__device__ __forceinline__ float warp_sum(float v){
    v += __shfl_xor_sync(0xffffffffu, v, 16);
    v += __shfl_xor_sync(0xffffffffu, v, 8);
    v += __shfl_xor_sync(0xffffffffu, v, 4);
    v += __shfl_xor_sync(0xffffffffu, v, 2);
    v += __shfl_xor_sync(0xffffffffu, v, 1);
    return v;
}

// ---------------------------------------------------------------------------
// Pass 1: per-atom Y values + radial f; each thread reduces HALF of the 294
// c-values over its warp (2 threads per atom -> shorter shuffle chains, 2x occ).
// ---------------------------------------------------------------------------
__global__ void __launch_bounds__(TPB1) pass1(const float* __restrict__ xyz){
    __shared__ float wsh[4][NC];   // per-32-atom-group partials
    const int t    = threadIdx.x;
    const int lane = t & 31;
    const int half = t >> 7;        // which half of the 294 values (b 0-2 vs 3-5)
    const int al   = t & 127;       // atom-local index
    const int wloc = al >> 5;       // 32-atom group 0..3
    const int j = blockIdx.x * APB + al;

    const float x = xyz[3*j+0], y = xyz[3*j+1], z = xyz[3*j+2];
    const float r2 = x*x + y*y + z*z;
    const float d  = sqrtf(r2);
    const float tc = 1.0f - d*RCINV;
    const float rcut = (d < RCF) ? tc*tc : 0.0f;

    // this thread's 3 radial values: b = half*3 + {0,1,2}
    float fh[3];
    {
        const float r6 = r2*r2*r2;
        fh[0] = rcut * (half ? r6 : 1.0f);
        fh[1] = fh[0]*r2;
        fh[2] = fh[1]*r2;
    }

    float re[LL][LL], im[LL][LL];
    re[0][0] = 0.28209479177387814f; im[0][0] = 0.0f;
    #pragma unroll
    for (int l = 1; l < LL; l++){
        const float alc = -sqrtf((2.0f*l + 1.0f)/(2.0f*l));
        re[l][l] = alc*(x*re[l-1][l-1] - y*im[l-1][l-1]);
        im[l][l] = alc*(x*im[l-1][l-1] + y*re[l-1][l-1]);
        #pragma unroll
        for (int m = 0; m < l; m++){
            const float invA = rsqrtf((float)(l*l - m*m)/((2.0f*l-1.0f)*(2.0f*l+1.0f)));
            if (l - 2 >= m){
                const float Ap = sqrtf((float)((l-1)*(l-1) - m*m)/((2.0f*l-3.0f)*(2.0f*l-1.0f)));
                re[l][m] = (z*re[l-1][m] - Ap*r2*re[l-2][m])*invA;
                im[l][m] = (z*im[l-1][m] - Ap*r2*im[l-2][m])*invA;
            } else {
                re[l][m] = z*re[l-1][m]*invA;
                im[l][m] = z*im[l-1][m]*invA;
            }
        }
    }

    const int vb = half*3*49;   // value index base for this half
    #pragma unroll
    for (int i = 0; i < LL; i++){
        #pragma unroll
        for (int jj = 0; jj < LL; jj++){
            const float yv = (jj <= i) ? re[i][i-jj] : im[jj][i+1];
            #pragma unroll
            for (int bb = 0; bb < 3; bb++){
                const float v = warp_sum(fh[bb]*yv);
                if (lane == 0) wsh[wloc][vb + bb*49 + i*7 + jj] = v;
            }
        }
    }
    __syncthreads();
    for (int v = t; v < NC; v += TPB1){
        g_part[blockIdx.x*NC + v] = wsh[0][v] + wsh[1][v] + wsh[2][v] + wsh[3][v];
    }
}

// ---------------------------------------------------------------------------
// Reduce 512 partials -> c, compute p (first 252 outputs). One 1024-thread block.
// ---------------------------------------------------------------------------
__global__ void __launch_bounds__(1024) reduce_c(float* __restrict__ out){
    __shared__ float part3[NC*3];
    __shared__ float csh[NC];
    const int t = threadIdx.x;
    if (t < NC*3){
        const int o = t/3, s = t%3;
        float sum = 0.0f;
        for (int p = s; p < NBLK1; p += 3) sum += g_part[p*NC + o];
        part3[t] = sum;
    }
    __syncthreads();
    if (t < NC){
        const float s = part3[t*3] + part3[t*3+1] + part3[t*3+2];
        g_c[t] = s;
        csh[t] = s;
    }
    __syncthreads();
    if (t < LL*NM*NM){   // 252
        const int l = t / 36;
        const int a = (t / 6) % 6;
        const int b = t % 6;
        const float* ca = &csh[a*49];
        const float* cb = &csh[b*49];
        float s = 0.0f;
        for (int m = 0; m <= l; m++){
            const float w = (m == l) ? 1.0f : 2.0f;
            s += w * ca[l*7 + m] * cb[l*7 + m];
        }
        for (int lp = 0; lp < l; lp++){
            s += 2.0f * ca[lp*7 + l] * cb[lp*7 + l];
        }
        out[t] = s;
    }
}

// ---------------------------------------------------------------------------
// Pass 2: dual recursion with ROLLING rows (only l-1, l-2 kept) -> no spills.
// ---------------------------------------------------------------------------

// accumulate G/H for row lv and emit the 36 symmetric (a,b) float3 streams
#define EMIT(lv) do {                                                          \
    float G[6]={0,0,0,0,0,0}, Hx[6]={0,0,0,0,0,0},                             \
          Hy[6]={0,0,0,0,0,0}, Hz[6]={0,0,0,0,0,0};                            \
    _Pragma("unroll")                                                          \
    for (int m = 0; m <= lv; m++){                                             \
        const float w = (m == 0) ? 1.0f : 2.0f;                                \
        _Pragma("unroll")                                                      \
        for (int b = 0; b < 6; b++){                                           \
            const float wc = w * csh[b*49 + lv*7 + (lv - m)];                  \
            G[b]  += wc*Rc[m].v;  Hx[b] += wc*Rc[m].gx;                        \
            Hy[b] += wc*Rc[m].gy; Hz[b] += wc*Rc[m].gz;                        \
        }                                                                      \
    }                                                                          \
    _Pragma("unroll")                                                          \
    for (int m = 1; m <= lv; m++){                                             \
        _Pragma("unroll")                                                      \
        for (int b = 0; b < 6; b++){                                           \
            const float wc = 2.0f * csh[b*49 + (m-1)*7 + lv];                  \
            G[b]  += wc*Ic[m].v;  Hx[b] += wc*Ic[m].gx;                        \
            Hy[b] += wc*Ic[m].gy; Hz[b] += wc*Ic[m].gz;                        \
        }                                                                      \
    }                                                                          \
    float* po = pbase + (size_t)(lv*36)*stride;                                \
    _Pragma("unroll")                                                          \
    for (int a = 0; a < 6; a++){                                               \
        _Pragma("unroll")                                                      \
        for (int b = a; b < 6; b++){                                           \
            const float vx = dfx[a]*G[b]+f[a]*Hx[b]+dfx[b]*G[a]+f[b]*Hx[a];    \
            const float vy = dfy[a]*G[b]+f[a]*Hy[b]+dfy[b]*G[a]+f[b]*Hy[a];    \
            const float vz = dfz[a]*G[b]+f[a]*Hz[b]+dfz[b]*G[a]+f[b]*Hz[a];    \
            float* p1 = po + (size_t)(a*6+b)*stride;                           \
            p1[0]=vx; p1[1]=vy; p1[2]=vz;                                      \
            if (a != b){                                                       \
                float* p2 = po + (size_t)(b*6+a)*stride;                       \
                p2[0]=vx; p2[1]=vy; p2[2]=vz;                                  \
            }                                                                  \
        }                                                                      \
    }                                                                          \
} while(0)

// recursion row lv from rows lv-1 (Rp/Ip) and lv-2 (Rp2/Ip2); rotates buffers
#define STEP(lv) do {                                                          \
    {                                                                          \
        const float alc = -sqrtf((2.0f*lv + 1.0f)/(2.0f*lv));                  \
        const D4 rp = Rp[lv-1], ip = Ip[lv-1];                                 \
        Rc[lv].v  = alc*(x*rp.v - y*ip.v);                                     \
        Rc[lv].gx = alc*(rp.v + x*rp.gx - y*ip.gx);                            \
        Rc[lv].gy = alc*(x*rp.gy - ip.v - y*ip.gy);                            \
        Rc[lv].gz = alc*(x*rp.gz - y*ip.gz);                                   \
        Ic[lv].v  = alc*(x*ip.v + y*rp.v);                                     \
        Ic[lv].gx = alc*(ip.v + x*ip.gx + y*rp.gx);                            \
        Ic[lv].gy = alc*(x*ip.gy + rp.v + y*rp.gy);                            \
        Ic[lv].gz = alc*(x*ip.gz + y*rp.gz);                                   \
    }                                                                          \
    _Pragma("unroll")                                                          \
    for (int m = 0; m < lv; m++){                                              \
        const float invA =                                                     \
            rsqrtf((float)(lv*lv - m*m)/((2.0f*lv-1.0f)*(2.0f*lv+1.0f)));      \
        const D4 a1r = Rp[m], a1i = Ip[m];                                     \
        if (lv - 2 >= m){                                                      \
            const float Ap = sqrtf((float)((lv-1)*(lv-1) - m*m)/               \
                                   ((2.0f*lv-3.0f)*(2.0f*lv-1.0f)));           \
            const D4 a2r = Rp2[m], a2i = Ip2[m];                               \
            Rc[m].v  = (z*a1r.v  - Ap*r2*a2r.v)*invA;                          \
            Rc[m].gx = (z*a1r.gx - Ap*(r2*a2r.gx + 2.0f*x*a2r.v))*invA;        \
            Rc[m].gy = (z*a1r.gy - Ap*(r2*a2r.gy + 2.0f*y*a2r.v))*invA;        \
            Rc[m].gz = (a1r.v + z*a1r.gz - Ap*(r2*a2r.gz + 2.0f*z*a2r.v))*invA;\
            Ic[m].v  = (z*a1i.v  - Ap*r2*a2i.v)*invA;                          \
            Ic[m].gx = (z*a1i.gx - Ap*(r2*a2i.gx + 2.0f*x*a2i.v))*invA;        \
            Ic[m].gy = (z*a1i.gy - Ap*(r2*a2i.gy + 2.0f*y*a2i.v))*invA;        \
            Ic[m].gz = (a1i.v + z*a1i.gz - Ap*(r2*a2i.gz + 2.0f*z*a2i.v))*invA;\
        } else {                                                               \
            Rc[m].v  = z*a1r.v*invA;                                           \
            Rc[m].gx = z*a1r.gx*invA;                                          \
            Rc[m].gy = z*a1r.gy*invA;                                          \
            Rc[m].gz = (a1r.v + z*a1r.gz)*invA;                                \
            Ic[m].v  = z*a1i.v*invA;                                           \
            Ic[m].gx = z*a1i.gx*invA;                                          \
            Ic[m].gy = z*a1i.gy*invA;                                          \
            Ic[m].gz = (a1i.v + z*a1i.gz)*invA;                                \
        }                                                                      \
    }                                                                          \
    _Pragma("unroll")                                                          \
    for (int m = 0; m < lv; m++){ Rp2[m]=Rp[m]; Ip2[m]=Ip[m]; }                \
    _Pragma("unroll")                                                          \
    for (int m = 0; m <= lv; m++){ Rp[m]=Rc[m]; Ip[m]=Ic[m]; }                 \
} while(0)

__global__ void __launch_bounds__(TPB2,1) pass2(const float* __restrict__ xyz,
                                                float* __restrict__ out){
    __shared__ float csh[NC];
    const int t = threadIdx.x;
    for (int i = t; i < NC; i += TPB2) csh[i] = g_c[i];
    __syncthreads();

    const int j = blockIdx.x * TPB2 + t;
    const float x = xyz[3*j+0], y = xyz[3*j+1], z = xyz[3*j+2];
    const float r2 = x*x + y*y + z*z;
    const float invd = rsqrtf(r2);
    const float d = r2 * invd;
    const float ux = x*invd, uy = y*invd, uz = z*invd;

    const float tc = 1.0f - d*RCINV;
    const bool  in = (d < RCF);
    const float rcut = in ? tc*tc : 0.0f;
    const float drc  = in ? (-2.0f*RCINV)*tc : 0.0f;

    float f[6], dfx[6], dfy[6], dfz[6];
    {
        float p2 = 1.0f;
        #pragma unroll
        for (int n = 0; n < 6; n++){
            f[n] = rcut * p2;
            const float dfn = drc*p2 + rcut * (2.0f*n) * p2 * invd;
            dfx[n] = dfn*ux; dfy[n] = dfn*uy; dfz[n] = dfn*uz;
            p2 *= r2;
        }
    }

    float* pbase = out + 252 + 3*(size_t)j;
    const size_t stride = (size_t)3 * NATOMS;

    D4 Rp[LL], Ip[LL], Rp2[LL], Ip2[LL], Rc[LL], Ic[LL];
    Rc[0].v = 0.28209479177387814f; Rc[0].gx = 0.f; Rc[0].gy = 0.f; Rc[0].gz = 0.f;
    Ic[0].v = 0.f; Ic[0].gx = 0.f; Ic[0].gy = 0.f; Ic[0].gz = 0.f;

    EMIT(0);
    Rp[0] = Rc[0]; Ip[0] = Ic[0];

    STEP(1); EMIT(1);
    STEP(2); EMIT(2);
    STEP(3); EMIT(3);
    STEP(4); EMIT(4);
    STEP(5); EMIT(5);
    STEP(6); EMIT(6);
}

// ---------------------------------------------------------------------------
extern "C" void kernel_launch(void* const* d_in, const int* in_sizes, int n_in,
                              void* d_out, int out_size){
    const float* xyz = (const float*)d_in[0];
    float* out = (float*)d_out;
    pass1<<<NBLK1, TPB1>>>(xyz);
    reduce_c<<<1, 1024>>>(out);
    pass2<<<NBLK2, TPB2>>>(xyz, out);
}

// round 3
// speedup vs baseline: 1.1904x; 1.1606x over previous
#include <cuda_runtime.h>
#include <math.h>

#define NATOMS 65536
#define NM     6
#define LL     7
#define NC     (NM*LL*LL)   // 294
#define RCF    6.0f
#define RCINV  (1.0f/6.0f)

// pass1: 2 threads per atom (each reduces 3 of the 6 radial channels)
#define TPB1   256
#define APB    128
#define NBLK1  (NATOMS/APB)  // 512

// pass2: 1 atom per thread
#define TPB2   128
#define NBLK2  (NATOMS/TPB2) // 512

__device__ float g_part[NBLK1 * NC];
__device__ float g_c[NC];

__device__ __forceinline__ float warp_sum(float v){
    v += __shfl_xor_sync(0xffffffffu, v, 16);
    v += __shfl_xor_sync(0xffffffffu, v, 8);
    v += __shfl_xor_sync(0xffffffffu, v, 4);
    v += __shfl_xor_sync(0xffffffffu, v, 2);
    v += __shfl_xor_sync(0xffffffffu, v, 1);
    return v;
}

// ---------------------------------------------------------------------------
// Pass 1: values-only recursion with ping-pong rows, emit per l.
// ---------------------------------------------------------------------------

// value-row step: dest RD/ID currently holds row lv-2 (read-before-write)
#define V_STEP(lv, RS, IS, RD, ID) do {                                        \
    _Pragma("unroll")                                                          \
    for (int m = 0; m < lv-1; m++){                                            \
        const float invA =                                                     \
            rsqrtf((float)(lv*lv - m*m)/((2.0f*lv-1.0f)*(2.0f*lv+1.0f)));      \
        const float Ap = sqrtf((float)((lv-1)*(lv-1) - m*m)/                   \
                               ((2.0f*lv-3.0f)*(2.0f*lv-1.0f)));               \
        const float o_r = RD[m], o_i = ID[m];                                  \
        RD[m] = (z*RS[m] - Ap*r2*o_r)*invA;                                    \
        ID[m] = (z*IS[m] - Ap*r2*o_i)*invA;                                    \
    }                                                                          \
    {   const int m = lv-1;                                                    \
        const float invA =                                                     \
            rsqrtf((float)(lv*lv - m*m)/((2.0f*lv-1.0f)*(2.0f*lv+1.0f)));      \
        RD[m] = z*RS[m]*invA;                                                  \
        ID[m] = z*IS[m]*invA;                                                  \
    }                                                                          \
    {   const float alc = -sqrtf((2.0f*lv + 1.0f)/(2.0f*lv));                  \
        RD[lv] = alc*(x*RS[lv-1] - y*IS[lv-1]);                                \
        ID[lv] = alc*(x*IS[lv-1] + y*RS[lv-1]);                                \
    }                                                                          \
} while(0)

// emit packed values of row lv: Re(l,m)->[l][l-m], Im(l,m)->[m-1][l]
#define V_EMIT(lv, RD, ID) do {                                                \
    _Pragma("unroll")                                                          \
    for (int m = 0; m <= lv; m++){                                             \
        const float yv = RD[m];                                                \
        _Pragma("unroll")                                                      \
        for (int bb = 0; bb < 3; bb++){                                        \
            const float v = warp_sum(fh[bb]*yv);                               \
            if (lane == 0) wsh[wloc][vb + bb*49 + lv*7 + (lv-m)] = v;          \
        }                                                                      \
    }                                                                          \
    _Pragma("unroll")                                                          \
    for (int m = 1; m <= lv; m++){                                             \
        const float yv = ID[m];                                                \
        _Pragma("unroll")                                                      \
        for (int bb = 0; bb < 3; bb++){                                        \
            const float v = warp_sum(fh[bb]*yv);                               \
            if (lane == 0) wsh[wloc][vb + bb*49 + (m-1)*7 + lv] = v;           \
        }                                                                      \
    }                                                                          \
} while(0)

__global__ void __launch_bounds__(TPB1) pass1(const float* __restrict__ xyz){
    __shared__ float wsh[4][NC];
    const int t    = threadIdx.x;
    const int lane = t & 31;
    const int half = t >> 7;
    const int al   = t & 127;
    const int wloc = al >> 5;
    const int vb   = half*3*49;
    const int j = blockIdx.x * APB + al;

    const float x = xyz[3*j+0], y = xyz[3*j+1], z = xyz[3*j+2];
    const float r2 = x*x + y*y + z*z;
    const float d  = sqrtf(r2);
    const float tc = 1.0f - d*RCINV;
    const float rcut = (d < RCF) ? tc*tc : 0.0f;

    float fh[3];
    {
        const float r6 = r2*r2*r2;
        fh[0] = rcut * (half ? r6 : 1.0f);
        fh[1] = fh[0]*r2;
        fh[2] = fh[1]*r2;
    }

    float RA[LL], IA[LL], RB[LL], IB[LL];
    RA[0] = 0.28209479177387814f; IA[0] = 0.0f;
    V_EMIT(0, RA, IA);
    // l=1 (no l-2 term): build B from A
    {
        const float invA = rsqrtf(1.0f/3.0f);
        RB[0] = z*RA[0]*invA;
        IB[0] = 0.0f;
        const float alc = -sqrtf(3.0f/2.0f);
        RB[1] = alc*(x*RA[0]);
        IB[1] = alc*(y*RA[0]);
    }
    V_EMIT(1, RB, IB);
    V_STEP(2, RB, IB, RA, IA); V_EMIT(2, RA, IA);
    V_STEP(3, RA, IA, RB, IB); V_EMIT(3, RB, IB);
    V_STEP(4, RB, IB, RA, IA); V_EMIT(4, RA, IA);
    V_STEP(5, RA, IA, RB, IB); V_EMIT(5, RB, IB);
    V_STEP(6, RB, IB, RA, IA); V_EMIT(6, RA, IA);

    __syncthreads();
    for (int v = t; v < NC; v += TPB1){
        g_part[blockIdx.x*NC + v] = wsh[0][v] + wsh[1][v] + wsh[2][v] + wsh[3][v];
    }
}

// ---------------------------------------------------------------------------
// Reduce 512 partials -> c, compute p (first 252 outputs). One block.
// ---------------------------------------------------------------------------
__global__ void __launch_bounds__(1024) reduce_c(float* __restrict__ out){
    __shared__ float part3[NC*3];
    __shared__ float csh[NC];
    const int t = threadIdx.x;
    if (t < NC*3){
        const int o = t/3, s = t%3;
        float sum = 0.0f;
        for (int p = s; p < NBLK1; p += 3) sum += g_part[p*NC + o];
        part3[t] = sum;
    }
    __syncthreads();
    if (t < NC){
        const float s = part3[t*3] + part3[t*3+1] + part3[t*3+2];
        g_c[t] = s;
        csh[t] = s;
    }
    __syncthreads();
    if (t < LL*NM*NM){   // 252
        const int l = t / 36;
        const int a = (t / 6) % 6;
        const int b = t % 6;
        const float* ca = &csh[a*49];
        const float* cb = &csh[b*49];
        float s = 0.0f;
        for (int m = 0; m <= l; m++){
            const float w = (m == l) ? 1.0f : 2.0f;
            s += w * ca[l*7 + m] * cb[l*7 + m];
        }
        for (int lp = 0; lp < l; lp++){
            s += 2.0f * ca[lp*7 + l] * cb[lp*7 + l];
        }
        out[t] = s;
    }
}

// ---------------------------------------------------------------------------
// Pass 2: dual recursion, ping-pong (row l overwrites row l-2), incremental
// radial factors inside the emit loop. 1 atom/thread, coalesced dp stores.
// ---------------------------------------------------------------------------

// dual row step: source row lv-1 in (RS*,IS*), dest holds row lv-2, overwritten
#define D_STEP(lv, RSv,RSx,RSy,RSz, ISv,ISx,ISy,ISz,                           \
                   RDv,RDx,RDy,RDz, IDv,IDx,IDy,IDz) do {                      \
    _Pragma("unroll")                                                          \
    for (int m = 0; m < lv-1; m++){                                            \
        const float invA =                                                     \
            rsqrtf((float)(lv*lv - m*m)/((2.0f*lv-1.0f)*(2.0f*lv+1.0f)));      \
        const float Ap = sqrtf((float)((lv-1)*(lv-1) - m*m)/                   \
                               ((2.0f*lv-3.0f)*(2.0f*lv-1.0f)));               \
        const float orv=RDv[m], orx=RDx[m], ory=RDy[m], orz=RDz[m];            \
        const float oiv=IDv[m], oix=IDx[m], oiy=IDy[m], oiz=IDz[m];            \
        RDv[m] = (z*RSv[m] - Ap*r2*orv)*invA;                                  \
        RDx[m] = (z*RSx[m] - Ap*(r2*orx + 2.0f*x*orv))*invA;                   \
        RDy[m] = (z*RSy[m] - Ap*(r2*ory + 2.0f*y*orv))*invA;                   \
        RDz[m] = (RSv[m] + z*RSz[m] - Ap*(r2*orz + 2.0f*z*orv))*invA;          \
        IDv[m] = (z*ISv[m] - Ap*r2*oiv)*invA;                                  \
        IDx[m] = (z*ISx[m] - Ap*(r2*oix + 2.0f*x*oiv))*invA;                   \
        IDy[m] = (z*ISy[m] - Ap*(r2*oiy + 2.0f*y*oiv))*invA;                   \
        IDz[m] = (ISv[m] + z*ISz[m] - Ap*(r2*oiz + 2.0f*z*oiv))*invA;          \
    }                                                                          \
    {   const int m = lv-1;                                                    \
        const float invA =                                                     \
            rsqrtf((float)(lv*lv - m*m)/((2.0f*lv-1.0f)*(2.0f*lv+1.0f)));      \
        RDv[m] = z*RSv[m]*invA;                                                \
        RDx[m] = z*RSx[m]*invA;                                                \
        RDy[m] = z*RSy[m]*invA;                                                \
        RDz[m] = (RSv[m] + z*RSz[m])*invA;                                     \
        IDv[m] = z*ISv[m]*invA;                                                \
        IDx[m] = z*ISx[m]*invA;                                                \
        IDy[m] = z*ISy[m]*invA;                                                \
        IDz[m] = (ISv[m] + z*ISz[m])*invA;                                     \
    }                                                                          \
    {   const float alc = -sqrtf((2.0f*lv + 1.0f)/(2.0f*lv));                  \
        const int p = lv-1;                                                    \
        RDv[lv] = alc*(x*RSv[p] - y*ISv[p]);                                   \
        RDx[lv] = alc*(RSv[p] + x*RSx[p] - y*ISx[p]);                          \
        RDy[lv] = alc*(x*RSy[p] - ISv[p] - y*ISy[p]);                          \
        RDz[lv] = alc*(x*RSz[p] - y*ISz[p]);                                   \
        IDv[lv] = alc*(x*ISv[p] + y*RSv[p]);                                   \
        IDx[lv] = alc*(ISv[p] + x*ISx[p] + y*RSx[p]);                          \
        IDy[lv] = alc*(x*ISy[p] + RSv[p] + y*RSy[p]);                          \
        IDz[lv] = alc*(x*ISz[p] + y*RSz[p]);                                   \
    }                                                                          \
} while(0)

#define D_EMIT(lv, RDv,RDx,RDy,RDz, IDv,IDx,IDy,IDz) do {                      \
    float G[6]={0,0,0,0,0,0}, Hx[6]={0,0,0,0,0,0},                             \
          Hy[6]={0,0,0,0,0,0}, Hz[6]={0,0,0,0,0,0};                            \
    _Pragma("unroll")                                                          \
    for (int m = 0; m <= lv; m++){                                             \
        const float w = (m == 0) ? 1.0f : 2.0f;                                \
        _Pragma("unroll")                                                      \
        for (int b = 0; b < 6; b++){                                           \
            const float wc = w * csh[b*49 + lv*7 + (lv - m)];                  \
            G[b]  += wc*RDv[m]; Hx[b] += wc*RDx[m];                            \
            Hy[b] += wc*RDy[m]; Hz[b] += wc*RDz[m];                            \
        }                                                                      \
    }                                                                          \
    _Pragma("unroll")                                                          \
    for (int m = 1; m <= lv; m++){                                             \
        _Pragma("unroll")                                                      \
        for (int b = 0; b < 6; b++){                                           \
            const float wc = 2.0f * csh[b*49 + (m-1)*7 + lv];                  \
            G[b]  += wc*IDv[m]; Hx[b] += wc*IDx[m];                            \
            Hy[b] += wc*IDy[m]; Hz[b] += wc*IDz[m];                            \
        }                                                                      \
    }                                                                          \
    float* po = pbase + (size_t)(lv*36)*stride;                                \
    float pa = 1.0f;                                                           \
    _Pragma("unroll")                                                          \
    for (int a = 0; a < 6; a++){                                               \
        const float fa  = rcut*pa;                                             \
        const float dca = pa*(drc + (2.0f*a)*rcut*invd);                       \
        float pb = pa;                                                         \
        _Pragma("unroll")                                                      \
        for (int b = a; b < 6; b++){                                           \
            const float fb  = rcut*pb;                                         \
            const float dcb = pb*(drc + (2.0f*b)*rcut*invd);                   \
            const float s  = dca*G[b] + dcb*G[a];                              \
            const float vx = ux*s + fa*Hx[b] + fb*Hx[a];                       \
            const float vy = uy*s + fa*Hy[b] + fb*Hy[a];                       \
            const float vz = uz*s + fa*Hz[b] + fb*Hz[a];                       \
            float* p1 = po + (size_t)(a*6+b)*stride;                           \
            p1[0]=vx; p1[1]=vy; p1[2]=vz;                                      \
            if (a != b){                                                       \
                float* p2 = po + (size_t)(b*6+a)*stride;                       \
                p2[0]=vx; p2[1]=vy; p2[2]=vz;                                  \
            }                                                                  \
            pb *= r2;                                                          \
        }                                                                      \
        pa *= r2;                                                              \
    }                                                                          \
} while(0)

__global__ void __launch_bounds__(TPB2,1) pass2(const float* __restrict__ xyz,
                                                float* __restrict__ out){
    __shared__ float csh[NC];
    const int t = threadIdx.x;
    for (int i = t; i < NC; i += TPB2) csh[i] = g_c[i];
    __syncthreads();

    const int j = blockIdx.x * TPB2 + t;
    const float x = xyz[3*j+0], y = xyz[3*j+1], z = xyz[3*j+2];
    const float r2 = x*x + y*y + z*z;
    const float invd = rsqrtf(r2);
    const float d = r2 * invd;
    const float ux = x*invd, uy = y*invd, uz = z*invd;

    const float tc = 1.0f - d*RCINV;
    const bool  in = (d < RCF);
    const float rcut = in ? tc*tc : 0.0f;
    const float drc  = in ? (-2.0f*RCINV)*tc : 0.0f;

    float* pbase = out + 252 + 3*(size_t)j;
    const size_t stride = (size_t)3 * NATOMS;

    // ping-pong dual rows: A and B, each [7] x (v,gx,gy,gz) x (re,im)
    float RAv[LL],RAx[LL],RAy[LL],RAz[LL], IAv[LL],IAx[LL],IAy[LL],IAz[LL];
    float RBv[LL],RBx[LL],RBy[LL],RBz[LL], IBv[LL],IBx[LL],IBy[LL],IBz[LL];

    RAv[0]=0.28209479177387814f; RAx[0]=0.f; RAy[0]=0.f; RAz[0]=0.f;
    IAv[0]=0.f; IAx[0]=0.f; IAy[0]=0.f; IAz[0]=0.f;
    D_EMIT(0, RAv,RAx,RAy,RAz, IAv,IAx,IAy,IAz);

    // l=1 from row 0 (no l-2 term)
    {
        const float invA = rsqrtf(1.0f/3.0f);
        RBv[0] = z*RAv[0]*invA; RBx[0]=0.f; RBy[0]=0.f; RBz[0]=RAv[0]*invA;
        IBv[0]=0.f; IBx[0]=0.f; IBy[0]=0.f; IBz[0]=0.f;
        const float alc = -sqrtf(3.0f/2.0f);
        RBv[1] = alc*x*RAv[0]; RBx[1]=alc*RAv[0]; RBy[1]=0.f; RBz[1]=0.f;
        IBv[1] = alc*y*RAv[0]; IBx[1]=0.f; IBy[1]=alc*RAv[0]; IBz[1]=0.f;
    }
    D_EMIT(1, RBv,RBx,RBy,RBz, IBv,IBx,IBy,IBz);

    D_STEP(2, RBv,RBx,RBy,RBz, IBv,IBx,IBy,IBz, RAv,RAx,RAy,RAz, IAv,IAx,IAy,IAz);
    D_EMIT(2, RAv,RAx,RAy,RAz, IAv,IAx,IAy,IAz);
    D_STEP(3, RAv,RAx,RAy,RAz, IAv,IAx,IAy,IAz, RBv,RBx,RBy,RBz, IBv,IBx,IBy,IBz);
    D_EMIT(3, RBv,RBx,RBy,RBz, IBv,IBx,IBy,IBz);
    D_STEP(4, RBv,RBx,RBy,RBz, IBv,IBx,IBy,IBz, RAv,RAx,RAy,RAz, IAv,IAx,IAy,IAz);
    D_EMIT(4, RAv,RAx,RAy,RAz, IAv,IAx,IAy,IAz);
    D_STEP(5, RAv,RAx,RAy,RAz, IAv,IAx,IAy,IAz, RBv,RBx,RBy,RBz, IBv,IBx,IBy,IBz);
    D_EMIT(5, RBv,RBx,RBy,RBz, IBv,IBx,IBy,IBz);
    D_STEP(6, RBv,RBx,RBy,RBz, IBv,IBx,IBy,IBz, RAv,RAx,RAy,RAz, IAv,IAx,IAy,IAz);
    D_EMIT(6, RAv,RAx,RAy,RAz, IAv,IAx,IAy,IAz);
}

// ---------------------------------------------------------------------------
extern "C" void kernel_launch(void* const* d_in, const int* in_sizes, int n_in,
                              void* d_out, int out_size){
    const float* xyz = (const float*)d_in[0];
    float* out = (float*)d_out;
    pass1<<<NBLK1, TPB1>>>(xyz);
    reduce_c<<<1, 1024>>>(out);
    pass2<<<NBLK2, TPB2>>>(xyz, out);
}

// round 4
// speedup vs baseline: 1.2872x; 1.0813x over previous
#include <cuda_runtime.h>
#include <math.h>

#define NATOMS 65536
#define NM     6
#define LL     7
#define NC     (NM*LL*LL)   // 294
#define RCF    6.0f
#define RCINV  (1.0f/6.0f)

// pass1: 2 threads per atom (each reduces 3 of the 6 radial channels)
#define TPB1   256
#define APB    128
#define NBLK1  (NATOMS/APB)  // 512

// pass2: 1 atom per thread
#define TPB2   128
#define NBLK2  (NATOMS/TPB2) // 512

__device__ float g_part[NBLK1 * NC];
__device__ float g_c[NC];

// ---------------------------------------------------------------------------
// Value-row recursion step (shared by both passes): dest holds row lv-2,
// overwritten in place (read-before-write).
// ---------------------------------------------------------------------------
#define V_STEP(lv, RS, IS, RD, ID) do {                                        \
    _Pragma("unroll")                                                          \
    for (int m = 0; m < lv-1; m++){                                            \
        const float invA =                                                     \
            rsqrtf((float)(lv*lv - m*m)/((2.0f*lv-1.0f)*(2.0f*lv+1.0f)));      \
        const float Ap = sqrtf((float)((lv-1)*(lv-1) - m*m)/                   \
                               ((2.0f*lv-3.0f)*(2.0f*lv-1.0f)));               \
        const float o_r = RD[m], o_i = ID[m];                                  \
        RD[m] = (z*RS[m] - Ap*r2*o_r)*invA;                                    \
        ID[m] = (z*IS[m] - Ap*r2*o_i)*invA;                                    \
    }                                                                          \
    {   const int m = lv-1;                                                    \
        const float invA =                                                     \
            rsqrtf((float)(lv*lv - m*m)/((2.0f*lv-1.0f)*(2.0f*lv+1.0f)));      \
        RD[m] = z*RS[m]*invA;                                                  \
        ID[m] = z*IS[m]*invA;                                                  \
    }                                                                          \
    {   const float alc = -sqrtf((2.0f*lv + 1.0f)/(2.0f*lv));                  \
        RD[lv] = alc*(x*RS[lv-1] - y*IS[lv-1]);                                \
        ID[lv] = alc*(x*IS[lv-1] + y*RS[lv-1]);                                \
    }                                                                          \
} while(0)

// ---------------------------------------------------------------------------
// Pass 1: values-only recursion; 2-stage warp reduction (8 coset partials).
// ---------------------------------------------------------------------------
#define P1_RED(val, idx) do {                                                  \
    float _v = (val);                                                          \
    _v += __shfl_xor_sync(0xffffffffu, _v, 16);                                \
    _v += __shfl_xor_sync(0xffffffffu, _v, 8);                                 \
    if (lane < 8) wsh[wloc][lane][idx] = _v;                                   \
} while(0)

#define V_EMIT(lv, RD, ID) do {                                                \
    _Pragma("unroll")                                                          \
    for (int m = 0; m <= lv; m++){                                             \
        const float yv = RD[m];                                                \
        _Pragma("unroll")                                                      \
        for (int bb = 0; bb < 3; bb++)                                         \
            P1_RED(fh[bb]*yv, vb + bb*49 + lv*7 + (lv-m));                     \
    }                                                                          \
    _Pragma("unroll")                                                          \
    for (int m = 1; m <= lv; m++){                                             \
        const float yv = ID[m];                                                \
        _Pragma("unroll")                                                      \
        for (int bb = 0; bb < 3; bb++)                                         \
            P1_RED(fh[bb]*yv, vb + bb*49 + (m-1)*7 + lv);                      \
    }                                                                          \
} while(0)

__global__ void __launch_bounds__(TPB1) pass1(const float* __restrict__ xyz){
    __shared__ float wsh[4][8][NC];
    const int t    = threadIdx.x;
    const int lane = t & 31;
    const int half = t >> 7;
    const int al   = t & 127;
    const int wloc = al >> 5;
    const int vb   = half*3*49;
    const int j = blockIdx.x * APB + al;

    const float x = xyz[3*j+0], y = xyz[3*j+1], z = xyz[3*j+2];
    const float r2 = x*x + y*y + z*z;
    const float d  = sqrtf(r2);
    const float tc = 1.0f - d*RCINV;
    const float rcut = (d < RCF) ? tc*tc : 0.0f;

    float fh[3];
    {
        const float r6 = r2*r2*r2;
        fh[0] = rcut * (half ? r6 : 1.0f);
        fh[1] = fh[0]*r2;
        fh[2] = fh[1]*r2;
    }

    float RA[LL], IA[LL], RB[LL], IB[LL];
    RA[0] = 0.28209479177387814f; IA[0] = 0.0f;
    V_EMIT(0, RA, IA);
    {
        const float sq3 = 1.7320508075688772f;       // 1/A(1,0)
        RB[0] = z*RA[0]*sq3;
        IB[0] = 0.0f;
        const float alc = -1.2247448713915890f;      // -sqrt(3/2)
        RB[1] = alc*(x*RA[0]);
        IB[1] = alc*(y*RA[0]);
    }
    V_EMIT(1, RB, IB);
    V_STEP(2, RB, IB, RA, IA); V_EMIT(2, RA, IA);
    V_STEP(3, RA, IA, RB, IB); V_EMIT(3, RB, IB);
    V_STEP(4, RB, IB, RA, IA); V_EMIT(4, RA, IA);
    V_STEP(5, RA, IA, RB, IB); V_EMIT(5, RB, IB);
    V_STEP(6, RB, IB, RA, IA); V_EMIT(6, RA, IA);

    __syncthreads();
    for (int v = t; v < NC; v += TPB1){
        float s = 0.0f;
        #pragma unroll
        for (int w = 0; w < 4; w++)
            #pragma unroll
            for (int c = 0; c < 8; c++)
                s += wsh[w][c][v];
        g_part[blockIdx.x*NC + v] = s;
    }
}

// ---------------------------------------------------------------------------
// Reduce 512 partials -> c, compute p (first 252 outputs). One block.
// ---------------------------------------------------------------------------
__global__ void __launch_bounds__(1024) reduce_c(float* __restrict__ out){
    __shared__ float part3[NC*3];
    __shared__ float csh[NC];
    const int t = threadIdx.x;
    if (t < NC*3){
        const int o = t/3, s = t%3;
        float sum = 0.0f;
        for (int p = s; p < NBLK1; p += 3) sum += g_part[p*NC + o];
        part3[t] = sum;
    }
    __syncthreads();
    if (t < NC){
        const float s = part3[t*3] + part3[t*3+1] + part3[t*3+2];
        g_c[t] = s;
        csh[t] = s;
    }
    __syncthreads();
    if (t < LL*NM*NM){   // 252
        const int l = t / 36;
        const int a = (t / 6) % 6;
        const int b = t % 6;
        const float* ca = &csh[a*49];
        const float* cb = &csh[b*49];
        float s = 0.0f;
        for (int m = 0; m <= l; m++){
            const float w = (m == l) ? 1.0f : 2.0f;
            s += w * ca[l*7 + m] * cb[l*7 + m];
        }
        for (int lp = 0; lp < l; lp++){
            s += 2.0f * ca[lp*7 + l] * cb[lp*7 + l];
        }
        out[t] = s;
    }
}

// ---------------------------------------------------------------------------
// Pass 2: values-only ping-pong recursion; gradients synthesized from row l-1
// via solid-harmonic lowering identities. Coalesced dp stores.
// ---------------------------------------------------------------------------
#define D_EMIT(lv, CR, CI, PR, PI) do {                                        \
    float G[6]={0,0,0,0,0,0}, Hx[6]={0,0,0,0,0,0},                             \
          Hy[6]={0,0,0,0,0,0}, Hz[6]={0,0,0,0,0,0};                            \
    _Pragma("unroll")                                                          \
    for (int m = 0; m <= lv; m++){                                             \
        const float az  = (m <= lv-1)                                          \
            ? sqrtf((float)((lv-m)*(lv+m))*(2.0f*lv+1.0f)/(2.0f*lv-1.0f))      \
            : 0.0f;                                                            \
        const float apH = (m+1 <= lv-1)                                        \
            ? 0.5f*sqrtf((float)((lv-m)*(lv-m-1))*(2.0f*lv+1.0f)/(2.0f*lv-1.0f))\
            : 0.0f;                                                            \
        const float amH = (lv >= 1 && (m >= 1 || lv >= 2))                     \
            ? 0.5f*sqrtf((float)((lv+m)*(lv+m-1))*(2.0f*lv+1.0f)/(2.0f*lv-1.0f))\
            : 0.0f;                                                            \
        const float prp = (m+1 <= lv-1) ? PR[m+1] : 0.0f;                      \
        const float pip = (m+1 <= lv-1) ? PI[m+1] : 0.0f;                      \
        const float prm = (m >= 1) ? PR[m-1] : ((lv >= 2) ? -PR[1] : 0.0f);    \
        const float pim = (m >= 1) ? PI[m-1] : ((lv >= 2) ?  PI[1] : 0.0f);    \
        const float pzr = (m <= lv-1) ? PR[m] : 0.0f;                          \
        const float pzi = (m <= lv-1) ? PI[m] : 0.0f;                          \
        const float gzr = az*pzr,                 gzi = az*pzi;                \
        const float gxr = apH*prp - amH*prm,      gxi = apH*pip - amH*pim;     \
        const float gyr = apH*pip + amH*pim,      gyi = -(apH*prp + amH*prm);  \
        const float w = (m == 0) ? 1.0f : 2.0f;                                \
        _Pragma("unroll")                                                      \
        for (int b = 0; b < 6; b++){                                           \
            const float wr = w * csh[b*49 + lv*7 + (lv - m)];                  \
            G[b]  += wr*CR[m]; Hx[b] += wr*gxr;                                \
            Hy[b] += wr*gyr;   Hz[b] += wr*gzr;                                \
        }                                                                      \
        if (m >= 1){                                                           \
            _Pragma("unroll")                                                  \
            for (int b = 0; b < 6; b++){                                       \
                const float wi = 2.0f * csh[b*49 + (m-1)*7 + lv];              \
                G[b]  += wi*CI[m]; Hx[b] += wi*gxi;                            \
                Hy[b] += wi*gyi;   Hz[b] += wi*gzi;                            \
            }                                                                  \
        }                                                                      \
    }                                                                          \
    float* po = pbase + (size_t)(lv*36)*stride;                                \
    float pa = 1.0f;                                                           \
    _Pragma("unroll")                                                          \
    for (int a = 0; a < 6; a++){                                               \
        const float fa  = rcut*pa;                                             \
        const float dca = pa*(drc + (2.0f*a)*rcut*invd);                       \
        float pb = pa;                                                         \
        _Pragma("unroll")                                                      \
        for (int b = a; b < 6; b++){                                           \
            const float fb  = rcut*pb;                                         \
            const float dcb = pb*(drc + (2.0f*b)*rcut*invd);                   \
            const float s  = dca*G[b] + dcb*G[a];                              \
            const float vx = ux*s + fa*Hx[b] + fb*Hx[a];                       \
            const float vy = uy*s + fa*Hy[b] + fb*Hy[a];                       \
            const float vz = uz*s + fa*Hz[b] + fb*Hz[a];                       \
            float* p1 = po + (size_t)(a*6+b)*stride;                           \
            p1[0]=vx; p1[1]=vy; p1[2]=vz;                                      \
            if (a != b){                                                       \
                float* p2 = po + (size_t)(b*6+a)*stride;                       \
                p2[0]=vx; p2[1]=vy; p2[2]=vz;                                  \
            }                                                                  \
            pb *= r2;                                                          \
        }                                                                      \
        pa *= r2;                                                              \
    }                                                                          \
} while(0)

__global__ void __launch_bounds__(TPB2) pass2(const float* __restrict__ xyz,
                                              float* __restrict__ out){
    __shared__ float csh[NC];
    const int t = threadIdx.x;
    for (int i = t; i < NC; i += TPB2) csh[i] = g_c[i];
    __syncthreads();

    const int j = blockIdx.x * TPB2 + t;
    const float x = xyz[3*j+0], y = xyz[3*j+1], z = xyz[3*j+2];
    const float r2 = x*x + y*y + z*z;
    const float invd = rsqrtf(r2);
    const float d = r2 * invd;
    const float ux = x*invd, uy = y*invd, uz = z*invd;

    const float tc = 1.0f - d*RCINV;
    const bool  in = (d < RCF);
    const float rcut = in ? tc*tc : 0.0f;
    const float drc  = in ? (-2.0f*RCINV)*tc : 0.0f;

    float* pbase = out + 252 + 3*(size_t)j;
    const size_t stride = (size_t)3 * NATOMS;

    float RA[LL], IA[LL], RB[LL], IB[LL];
    RA[0] = 0.28209479177387814f; IA[0] = 0.0f;
    D_EMIT(0, RA, IA, RB, IB);        // prev unused (all terms compile to 0)

    {
        const float sq3 = 1.7320508075688772f;
        RB[0] = z*RA[0]*sq3;
        IB[0] = 0.0f;
        const float alc = -1.2247448713915890f;
        RB[1] = alc*(x*RA[0]);
        IB[1] = alc*(y*RA[0]);
    }
    D_EMIT(1, RB, IB, RA, IA);

    V_STEP(2, RB, IB, RA, IA); D_EMIT(2, RA, IA, RB, IB);
    V_STEP(3, RA, IA, RB, IB); D_EMIT(3, RB, IB, RA, IA);
    V_STEP(4, RB, IB, RA, IA); D_EMIT(4, RA, IA, RB, IB);
    V_STEP(5, RA, IA, RB, IB); D_EMIT(5, RB, IB, RA, IA);
    V_STEP(6, RB, IB, RA, IA); D_EMIT(6, RA, IA, RB, IB);
}

// ---------------------------------------------------------------------------
extern "C" void kernel_launch(void* const* d_in, const int* in_sizes, int n_in,
                              void* d_out, int out_size){
    const float* xyz = (const float*)d_in[0];
    float* out = (float*)d_out;
    pass1<<<NBLK1, TPB1>>>(xyz);
    reduce_c<<<1, 1024>>>(out);
    pass2<<<NBLK2, TPB2>>>(xyz, out);
}

// round 7
// speedup vs baseline: 1.4474x; 1.1245x over previous
#include <cuda_runtime.h>
#include <math.h>

#define NATOMS 65536
#define NM     6
#define LL     7
#define NC     (NM*LL*LL)   // 294
#define RCF    6.0f
#define RCINV  (1.0f/6.0f)

// pass1: 2 threads per atom, 64 atoms per 128-thread block
#define TPB1   128
#define APB    64
#define NBLK1  (NATOMS/APB)   // 1024

// pass2: 1 atom per thread, 128 atoms per block
#define TPB2   128
#define NBLK2  (NATOMS/TPB2)  // 512

__device__ float g_part[NBLK1 * NC];
__device__ float g_c[NC];

// ---------------------------------------------------------------------------
// Value-row recursion step: dest holds row lv-2, overwritten in place.
// ---------------------------------------------------------------------------
#define V_STEP(lv, RS, IS, RD, ID) do {                                        \
    _Pragma("unroll")                                                          \
    for (int m = 0; m < lv-1; m++){                                            \
        const float invA =                                                     \
            rsqrtf((float)(lv*lv - m*m)/((2.0f*lv-1.0f)*(2.0f*lv+1.0f)));      \
        const float Ap = sqrtf((float)((lv-1)*(lv-1) - m*m)/                   \
                               ((2.0f*lv-3.0f)*(2.0f*lv-1.0f)));               \
        const float o_r = RD[m], o_i = ID[m];                                  \
        RD[m] = (z*RS[m] - Ap*r2*o_r)*invA;                                    \
        ID[m] = (z*IS[m] - Ap*r2*o_i)*invA;                                    \
    }                                                                          \
    {   const int m = lv-1;                                                    \
        const float invA =                                                     \
            rsqrtf((float)(lv*lv - m*m)/((2.0f*lv-1.0f)*(2.0f*lv+1.0f)));      \
        RD[m] = z*RS[m]*invA;                                                  \
        ID[m] = z*IS[m]*invA;                                                  \
    }                                                                          \
    {   const float alc = -sqrtf((2.0f*lv + 1.0f)/(2.0f*lv));                  \
        RD[lv] = alc*(x*RS[lv-1] - y*IS[lv-1]);                                \
        ID[lv] = alc*(x*IS[lv-1] + y*RS[lv-1]);                                \
    }                                                                          \
} while(0)

// ---------------------------------------------------------------------------
// Pass 1: values-only recursion; 2-stage warp reduction (8 coset partials).
// ---------------------------------------------------------------------------
#define P1_RED(val, idx) do {                                                  \
    float _v = (val);                                                          \
    _v += __shfl_xor_sync(0xffffffffu, _v, 16);                                \
    _v += __shfl_xor_sync(0xffffffffu, _v, 8);                                 \
    if (lane < 8) wsh[wloc][lane][idx] = _v;                                   \
} while(0)

#define V_EMIT(lv, RD, ID) do {                                                \
    _Pragma("unroll")                                                          \
    for (int m = 0; m <= lv; m++){                                             \
        const float yv = RD[m];                                                \
        _Pragma("unroll")                                                      \
        for (int bb = 0; bb < 3; bb++)                                         \
            P1_RED(fh[bb]*yv, vb + bb*49 + lv*7 + (lv-m));                     \
    }                                                                          \
    _Pragma("unroll")                                                          \
    for (int m = 1; m <= lv; m++){                                             \
        const float yv = ID[m];                                                \
        _Pragma("unroll")                                                      \
        for (int bb = 0; bb < 3; bb++)                                         \
            P1_RED(fh[bb]*yv, vb + bb*49 + (m-1)*7 + lv);                      \
    }                                                                          \
} while(0)

__global__ void __launch_bounds__(TPB1) pass1(const float* __restrict__ xyz){
    __shared__ float wsh[2][8][NC];
    const int t    = threadIdx.x;
    const int lane = t & 31;
    const int half = t >> 6;        // 0..1: which 3 radial channels
    const int al   = t & 63;        // atom-local
    const int wloc = al >> 5;       // 0..1
    const int vb   = half*3*49;
    const int j = blockIdx.x * APB + al;

    const float x = xyz[3*j+0], y = xyz[3*j+1], z = xyz[3*j+2];
    const float r2 = x*x + y*y + z*z;
    const float d  = sqrtf(r2);
    const float tc = 1.0f - d*RCINV;
    const float rcut = (d < RCF) ? tc*tc : 0.0f;

    float fh[3];
    {
        const float r6 = r2*r2*r2;
        fh[0] = rcut * (half ? r6 : 1.0f);
        fh[1] = fh[0]*r2;
        fh[2] = fh[1]*r2;
    }

    float RA[LL], IA[LL], RB[LL], IB[LL];
    RA[0] = 0.28209479177387814f; IA[0] = 0.0f;
    V_EMIT(0, RA, IA);
    {
        const float sq3 = 1.7320508075688772f;
        RB[0] = z*RA[0]*sq3;
        IB[0] = 0.0f;
        const float alc = -1.2247448713915890f;
        RB[1] = alc*(x*RA[0]);
        IB[1] = alc*(y*RA[0]);
    }
    V_EMIT(1, RB, IB);
    V_STEP(2, RB, IB, RA, IA); V_EMIT(2, RA, IA);
    V_STEP(3, RA, IA, RB, IB); V_EMIT(3, RB, IB);
    V_STEP(4, RB, IB, RA, IA); V_EMIT(4, RA, IA);
    V_STEP(5, RA, IA, RB, IB); V_EMIT(5, RB, IB);
    V_STEP(6, RB, IB, RA, IA); V_EMIT(6, RA, IA);

    __syncthreads();
    for (int v = t; v < NC; v += TPB1){
        float s = 0.0f;
        #pragma unroll
        for (int w = 0; w < 2; w++)
            #pragma unroll
            for (int c = 0; c < 8; c++)
                s += wsh[w][c][v];
        g_part[blockIdx.x*NC + v] = s;
    }
}

// ---------------------------------------------------------------------------
// Reduce 1024 partials -> c, compute p (first 252 outputs). One block.
// ---------------------------------------------------------------------------
__global__ void __launch_bounds__(1024) reduce_c(float* __restrict__ out){
    __shared__ float part3[NC*3];
    __shared__ float csh[NC];
    const int t = threadIdx.x;
    if (t < NC*3){
        const int o = t/3, s = t%3;
        float sum = 0.0f;
        for (int p = s; p < NBLK1; p += 3) sum += g_part[p*NC + o];
        part3[t] = sum;
    }
    __syncthreads();
    if (t < NC){
        const float s = part3[t*3] + part3[t*3+1] + part3[t*3+2];
        g_c[t] = s;
        csh[t] = s;
    }
    __syncthreads();
    if (t < LL*NM*NM){   // 252
        const int l = t / 36;
        const int a = (t / 6) % 6;
        const int b = t % 6;
        const float* ca = &csh[a*49];
        const float* cb = &csh[b*49];
        float s = 0.0f;
        for (int m = 0; m <= l; m++){
            const float w = (m == l) ? 1.0f : 2.0f;
            s += w * ca[l*7 + m] * cb[l*7 + m];
        }
        for (int lp = 0; lp < l; lp++){
            s += 2.0f * ca[lp*7 + l] * cb[lp*7 + l];
        }
        out[t] = s;
    }
}

// ---------------------------------------------------------------------------
// Pass 2: values-only ping-pong recursion; gradients synthesized from row l-1.
// dp written via smem staging -> aligned float4 streaming stores.
// ---------------------------------------------------------------------------

// pair index for a<=b among 21: P = a*6 - a*(a+1)/2 + b
__device__ __forceinline__ int pair_idx(int a, int b){
    return a*6 - (a*(a+1))/2 + b;
}

#define D_EMIT(lv, CR, CI, PR, PI) do {                                        \
    float G[6]={0,0,0,0,0,0}, Hx[6]={0,0,0,0,0,0},                             \
          Hy[6]={0,0,0,0,0,0}, Hz[6]={0,0,0,0,0,0};                            \
    _Pragma("unroll")                                                          \
    for (int m = 0; m <= lv; m++){                                             \
        const float az  = (m <= lv-1)                                          \
            ? sqrtf((float)((lv-m)*(lv+m))*(2.0f*lv+1.0f)/(2.0f*lv-1.0f))      \
            : 0.0f;                                                            \
        const float apH = (m+1 <= lv-1)                                        \
            ? 0.5f*sqrtf((float)((lv-m)*(lv-m-1))*(2.0f*lv+1.0f)/(2.0f*lv-1.0f))\
            : 0.0f;                                                            \
        const float amH = (lv >= 1 && (m >= 1 || lv >= 2))                     \
            ? 0.5f*sqrtf((float)((lv+m)*(lv+m-1))*(2.0f*lv+1.0f)/(2.0f*lv-1.0f))\
            : 0.0f;                                                            \
        const float prp = (m+1 <= lv-1) ? PR[m+1] : 0.0f;                      \
        const float pip = (m+1 <= lv-1) ? PI[m+1] : 0.0f;                      \
        const float prm = (m >= 1) ? PR[m-1] : ((lv >= 2) ? -PR[1] : 0.0f);    \
        const float pim = (m >= 1) ? PI[m-1] : ((lv >= 2) ?  PI[1] : 0.0f);    \
        const float pzr = (m <= lv-1) ? PR[m] : 0.0f;                          \
        const float pzi = (m <= lv-1) ? PI[m] : 0.0f;                          \
        const float gzr = az*pzr,                 gzi = az*pzi;                \
        const float gxr = apH*prp - amH*prm,      gxi = apH*pip - amH*pim;     \
        const float gyr = apH*pip + amH*pim,      gyi = -(apH*prp + amH*prm);  \
        const float w = (m == 0) ? 1.0f : 2.0f;                                \
        _Pragma("unroll")                                                      \
        for (int b = 0; b < 6; b++){                                           \
            const float wr = w * csh[b*49 + lv*7 + (lv - m)];                  \
            G[b]  += wr*CR[m]; Hx[b] += wr*gxr;                                \
            Hy[b] += wr*gyr;   Hz[b] += wr*gzr;                                \
        }                                                                      \
        if (m >= 1){                                                           \
            _Pragma("unroll")                                                  \
            for (int b = 0; b < 6; b++){                                       \
                const float wi = 2.0f * csh[b*49 + (m-1)*7 + lv];              \
                G[b]  += wi*CI[m]; Hx[b] += wi*gxi;                            \
                Hy[b] += wi*gyi;   Hz[b] += wi*gzi;                            \
            }                                                                  \
        }                                                                      \
    }                                                                          \
    /* stage 21 unique pairs into shared */                                    \
    float pa = 1.0f;                                                           \
    _Pragma("unroll")                                                          \
    for (int a = 0; a < 6; a++){                                               \
        const float fa  = rcut*pa;                                             \
        const float dca = pa*(drc + (2.0f*a)*rcut*invd);                       \
        float pb = pa;                                                         \
        _Pragma("unroll")                                                      \
        for (int b = a; b < 6; b++){                                           \
            const float fb  = rcut*pb;                                         \
            const float dcb = pb*(drc + (2.0f*b)*rcut*invd);                   \
            const float s  = dca*G[b] + dcb*G[a];                              \
            float* sp = &stage[pair_idx(a,b)][3*t];                            \
            sp[0] = ux*s + fa*Hx[b] + fb*Hx[a];                                \
            sp[1] = uy*s + fa*Hy[b] + fb*Hy[a];                                \
            sp[2] = uz*s + fa*Hz[b] + fb*Hz[a];                                \
            pb *= r2;                                                          \
        }                                                                      \
        pa *= r2;                                                              \
    }                                                                          \
    __syncthreads();                                                           \
    /* cooperative aligned float4 streaming write-out of 36 streams */         \
    {                                                                          \
        float* lbase = out + 252 + (size_t)(lv*36)*stride + (size_t)blockIdx.x*(TPB2*3); \
        _Pragma("unroll")                                                      \
        for (int k = 0; k < 27; k++){                                          \
            const int e = t + k*TPB2;            /* 0..3455 */                 \
            const int s36 = e / 96;                                            \
            const int q   = e - s36*96;                                        \
            const int a = s36 / 6, b = s36 % 6;                                \
            const int p = (a <= b) ? pair_idx(a,b) : pair_idx(b,a);            \
            const float4 v = *(const float4*)&stage[p][q*4];                   \
            __stcs((float4*)(lbase + (size_t)s36*stride) + q, v);              \
        }                                                                      \
    }                                                                          \
    __syncthreads();                                                           \
} while(0)

__global__ void __launch_bounds__(TPB2) pass2(const float* __restrict__ xyz,
                                              float* __restrict__ out){
    __shared__ __align__(16) float stage[21][TPB2*3];
    __shared__ float csh[NC];
    const int t = threadIdx.x;
    for (int i = t; i < NC; i += TPB2) csh[i] = g_c[i];
    __syncthreads();

    const int j = blockIdx.x * TPB2 + t;
    const float x = xyz[3*j+0], y = xyz[3*j+1], z = xyz[3*j+2];
    const float r2 = x*x + y*y + z*z;
    const float invd = rsqrtf(r2);
    const float d = r2 * invd;
    const float ux = x*invd, uy = y*invd, uz = z*invd;

    const float tc = 1.0f - d*RCINV;
    const bool  in = (d < RCF);
    const float rcut = in ? tc*tc : 0.0f;
    const float drc  = in ? (-2.0f*RCINV)*tc : 0.0f;

    const size_t stride = (size_t)3 * NATOMS;

    float RA[LL], IA[LL], RB[LL], IB[LL];
    RA[0] = 0.28209479177387814f; IA[0] = 0.0f;
    D_EMIT(0, RA, IA, RB, IB);

    {
        const float sq3 = 1.7320508075688772f;
        RB[0] = z*RA[0]*sq3;
        IB[0] = 0.0f;
        const float alc = -1.2247448713915890f;
        RB[1] = alc*(x*RA[0]);
        IB[1] = alc*(y*RA[0]);
    }
    D_EMIT(1, RB, IB, RA, IA);

    V_STEP(2, RB, IB, RA, IA); D_EMIT(2, RA, IA, RB, IB);
    V_STEP(3, RA, IA, RB, IB); D_EMIT(3, RB, IB, RA, IA);
    V_STEP(4, RB, IB, RA, IA); D_EMIT(4, RA, IA, RB, IB);
    V_STEP(5, RA, IA, RB, IB); D_EMIT(5, RB, IB, RA, IA);
    V_STEP(6, RB, IB, RA, IA); D_EMIT(6, RA, IA, RB, IB);
}

// ---------------------------------------------------------------------------
extern "C" void kernel_launch(void* const* d_in, const int* in_sizes, int n_in,
                              void* d_out, int out_size){
    const float* xyz = (const float*)d_in[0];
    float* out = (float*)d_out;
    pass1<<<NBLK1, TPB1>>>(xyz);
    reduce_c<<<1, 1024>>>(out);
    pass2<<<NBLK2, TPB2>>>(xyz, out);
}